// round 2
// baseline (speedup 1.0000x reference)
#include <cuda_runtime.h>
#include <math.h>

#define VOCAB 50257
#define EMB   128

// ---------------- scratch (no allocations allowed) ----------------
__device__ float    g_s[VOCAB];        // column sums of text_onehot
__device__ float    g_hpart[2][EMB];   // partial hidden (2 v-segments)
__device__ float    g_logits[VOCAB];
__device__ unsigned g_gmax;            // flipped-float encoded max
__device__ float    g_zpart[256];      // partial exp-sums

// monotone float<->uint mapping for atomicMax
__device__ __forceinline__ unsigned flipf(float f) {
    unsigned u = __float_as_uint(f);
    return (u & 0x80000000u) ? ~u : (u | 0x80000000u);
}
__device__ __forceinline__ float unflipf(unsigned u) {
    u = (u & 0x80000000u) ? (u ^ 0x80000000u) : ~u;
    return __uint_as_float(u);
}

__device__ __forceinline__ float blockReduceSum(float v, float* sm) {
    int lane = threadIdx.x & 31, warp = threadIdx.x >> 5;
#pragma unroll
    for (int o = 16; o; o >>= 1) v += __shfl_xor_sync(0xffffffffu, v, o);
    if (lane == 0) sm[warp] = v;
    __syncthreads();
    int nw = blockDim.x >> 5;
    v = (warp == 0 && lane < nw) ? sm[lane] : 0.f;
    if (warp == 0) {
#pragma unroll
        for (int o = 16; o; o >>= 1) v += __shfl_xor_sync(0xffffffffu, v, o);
    }
    return v;  // valid on thread 0
}

// ---------------- K1: s[v] = sum_t onehot[t][v] ----------------
// 256 threads = 64 v-lanes x 4 t-groups. Coalesced 128B lines per warp per t.
__global__ void k1_colsum(const float* __restrict__ oh, int rows) {
    __shared__ float sm[256];
    const int vloc = threadIdx.x & 63;
    const int tg   = threadIdx.x >> 6;          // 0..3
    const int v    = blockIdx.x * 64 + vloc;
    float acc = 0.f;
    if (v < VOCAB) {
        const int rp = (rows + 3) >> 2;
        const int t0 = tg * rp;
        const int t1 = min(rows, t0 + rp);
        const float* p = oh + (size_t)t0 * VOCAB + v;
#pragma unroll 10
        for (int t = t0; t < t1; ++t) { acc += *p; p += VOCAB; }
    }
    sm[threadIdx.x] = acc;
    __syncthreads();
    if (threadIdx.x < 64 && v < VOCAB) {
        g_s[v] = sm[threadIdx.x] + sm[threadIdx.x + 64]
               + sm[threadIdx.x + 128] + sm[threadIdx.x + 192];
    }
}

// ---------------- K2: hidden[e] = (1/L) sum_v s[v]*Wq[e,v] + bq[e] ----------------
// grid (2 v-segments, 128 e). Each block: 512 threads stream one Wq row segment.
__global__ void k2_hidden(const float* __restrict__ Wq, const float* __restrict__ bq,
                          float inv_len) {
    __shared__ float sm[16];
    const int e   = blockIdx.y;
    const int seg = blockIdx.x;
    const int segsz = (VOCAB + 1) >> 1;
    const int vlo = seg * segsz;
    const int vhi = min(VOCAB, vlo + segsz);
    const float* wr = Wq + (size_t)e * VOCAB;
    float acc = 0.f;
#pragma unroll 4
    for (int v = vlo + threadIdx.x; v < vhi; v += 512)
        acc += g_s[v] * __ldg(wr + v);
    acc = blockReduceSum(acc, sm);
    if (threadIdx.x == 0) {
        g_hpart[seg][e] = acc * inv_len + (seg == 0 ? bq[e] : 0.f);
        if (e == 0 && seg == 0) g_gmax = 0u;   // init for K3's atomicMax
    }
}

// ---------------- K3: logits[v] = dot(hidden, Ww[v]) + bw[v]; track max ----------------
// warp-per-row, 8 rows/warp, 8 warps/block -> 64 rows/block, float4 loads.
__global__ void k3_logits(const float* __restrict__ Ww, const float* __restrict__ bw) {
    __shared__ float sh[EMB];
    __shared__ float shmax[8];
    const int tid = threadIdx.x;
    if (tid < EMB) sh[tid] = g_hpart[0][tid] + g_hpart[1][tid];
    __syncthreads();
    const int lane = tid & 31, warp = tid >> 5;
    const float4 h4 = reinterpret_cast<const float4*>(sh)[lane];
    const int vbase = (blockIdx.x * 8 + warp) * 8;
    float wmax = -3.402823466e38f;
#pragma unroll
    for (int r = 0; r < 8; ++r) {
        int v = vbase + r;
        if (v < VOCAB) {   // uniform per warp
            float4 w4 = reinterpret_cast<const float4*>(Ww + (size_t)v * EMB)[lane];
            float p = w4.x * h4.x + w4.y * h4.y + w4.z * h4.z + w4.w * h4.w;
#pragma unroll
            for (int o = 16; o; o >>= 1) p += __shfl_xor_sync(0xffffffffu, p, o);
            float lg = p + __ldg(bw + v);
            if (lane == 0) g_logits[v] = lg;
            wmax = fmaxf(wmax, lg);
        }
    }
    if (lane == 0) shmax[warp] = wmax;
    __syncthreads();
    if (tid == 0) {
        float m = shmax[0];
#pragma unroll
        for (int i = 1; i < 8; ++i) m = fmaxf(m, shmax[i]);
        atomicMax(&g_gmax, flipf(m));
    }
}

// ---------------- K4: partial sums of exp(logit - max) ----------------
#define NZ ((VOCAB + 255) / 256)   // 197
__global__ void k4_sumexp() {
    __shared__ float sm[8];
    const int v = blockIdx.x * 256 + threadIdx.x;
    const float m = unflipf(g_gmax);
    float e = 0.f;
    if (v < VOCAB) e = expf(g_logits[v] - m);
    e = blockReduceSum(e, sm);
    if (threadIdx.x == 0) g_zpart[blockIdx.x] = e;
}

// ---------------- K5: out[v] = logits[v] - (max + log(Z)) ----------------
__global__ void k5_out(float* __restrict__ out) {
    __shared__ float sm[8];
    __shared__ float s_lse;
    float z = 0.f;
    for (int i = threadIdx.x; i < NZ; i += 256) z += g_zpart[i];
    z = blockReduceSum(z, sm);
    if (threadIdx.x == 0) s_lse = logf(z) + unflipf(g_gmax);
    __syncthreads();
    const int v = blockIdx.x * 256 + threadIdx.x;
    if (v < VOCAB) out[v] = g_logits[v] - s_lse;
}

// ---------------- launch ----------------
extern "C" void kernel_launch(void* const* d_in, const int* in_sizes, int n_in,
                              void* d_out, int out_size) {
    const float* oh = (const float*)d_in[0];
    // d_in[1] is the scalar `length` (== CTX); derive rows from shape instead
    const float* Wq = (const float*)d_in[2];
    const float* bq = (const float*)d_in[3];
    const float* Ww = (const float*)d_in[4];
    const float* bw = (const float*)d_in[5];
    float* out = (float*)d_out;

    const int rows = in_sizes[0] / VOCAB;        // 200
    const float inv_len = 1.0f / (float)rows;    // length == CTX in this problem

    k1_colsum<<<(VOCAB + 63) / 64, 256>>>(oh, rows);
    dim3 g2(2, EMB);
    k2_hidden<<<g2, 512>>>(Wq, bq, inv_len);
    k3_logits<<<(VOCAB + 63) / 64, 256>>>(Ww, bw);
    k4_sumexp<<<NZ, 256>>>();
    k5_out<<<NZ, 256>>>(out);
}

// round 3
// speedup vs baseline: 1.0836x; 1.0836x over previous
#include <cuda_runtime.h>
#include <math.h>

#define VOCAB 50257
#define EMB   128
#define GRID  592          // <= 148 SMs * 8 guaranteed-resident blocks -> fully co-resident
#define NB1   197          // phase-1 v-blocks (197*256 = 50432 >= VOCAB)
#define TSEG  3            // phase-1 t-segments
#define CHUNK4 ((VOCAB + 3) / 4)   // 12565
#define VPB   85           // v per block in phase 3/4 (592*85 = 50320 >= VOCAB)

// ---------------- persistent scratch (no allocations allowed) ----------------
__device__ float    g_sp[TSEG][NB1 * 256];  // phase-1 partial column sums
__device__ float    g_s[VOCAB];             // folded column sums
__device__ float    g_hp[4][EMB];           // hidden partials (4 v-chunks)
__device__ float    g_m[GRID];              // per-block logit max
__device__ float    g_z[GRID];              // per-block sum exp(l - m_b)
__device__ unsigned g_barrier = 0;          // monotone arrival counter (reset each run)
__device__ unsigned g_done    = 0;          // completion counter for reset

// ---------------- grid barrier (all GRID blocks guaranteed co-resident) -----
__device__ __forceinline__ void grid_bar(unsigned target) {
    __syncthreads();
    if (threadIdx.x == 0) {
        __threadfence();
        atomicAdd(&g_barrier, 1u);
        volatile unsigned* p = &g_barrier;
        while (*p < target) { }
        __threadfence();
    }
    __syncthreads();
}

// ---------------- block reductions (fixed order -> deterministic) -----------
__device__ __forceinline__ float blockReduceSum(float v, float* sm) {
    int lane = threadIdx.x & 31, warp = threadIdx.x >> 5;
#pragma unroll
    for (int o = 16; o; o >>= 1) v += __shfl_xor_sync(0xffffffffu, v, o);
    if (lane == 0) sm[warp] = v;
    __syncthreads();
    v = (warp == 0 && lane < 8) ? sm[lane] : 0.f;
    if (warp == 0) {
#pragma unroll
        for (int o = 4; o; o >>= 1) v += __shfl_xor_sync(0xffffffffu, v, o);
    }
    return v;  // valid on thread 0
}

__device__ __forceinline__ float blockReduceMax(float v, float* sm) {
    int lane = threadIdx.x & 31, warp = threadIdx.x >> 5;
#pragma unroll
    for (int o = 16; o; o >>= 1) v = fmaxf(v, __shfl_xor_sync(0xffffffffu, v, o));
    if (lane == 0) sm[warp] = v;
    __syncthreads();
    v = (warp == 0 && lane < 8) ? sm[lane] : -3.402823466e38f;
    if (warp == 0) {
#pragma unroll
        for (int o = 4; o; o >>= 1) v = fmaxf(v, __shfl_xor_sync(0xffffffffu, v, o));
    }
    return v;  // valid on thread 0
}

// ---------------- the single persistent kernel ------------------------------
__global__ void __launch_bounds__(256, 8)
w2v_persist(const float* __restrict__ oh, const float* __restrict__ Wq,
            const float* __restrict__ bq, const float* __restrict__ Ww,
            const float* __restrict__ bw, float* __restrict__ out,
            int rows, float inv_len)
{
    __shared__ float sh_hid[EMB];
    __shared__ float sh_log[96];
    __shared__ float sh_red[8];
    __shared__ float sh_bc;

    const int tid = threadIdx.x;
    const int b   = blockIdx.x;

    // ===== Phase 1: partial column sums of text_onehot (3 t-segments) =====
    {
        const int seg = b / NB1;                 // 0..2 for b<591, seg==3 -> idle
        if (seg < TSEG) {
            const int v = (b - seg * NB1) * 256 + tid;
            if (v < VOCAB) {
                const int rp = (rows + TSEG - 1) / TSEG;
                const int t0 = seg * rp;
                const int t1 = min(rows, t0 + rp);
                const size_t S = (size_t)VOCAB;
                const float* p = oh + (size_t)t0 * S + v;
                float acc = 0.f;
                int n = t1 - t0, i = 0;
                for (; i + 8 <= n; i += 8) {
                    float a0 = p[0*S], a1 = p[1*S], a2 = p[2*S], a3 = p[3*S];
                    float a4 = p[4*S], a5 = p[5*S], a6 = p[6*S], a7 = p[7*S];
                    acc += ((a0 + a1) + (a2 + a3)) + ((a4 + a5) + (a6 + a7));
                    p += 8 * S;
                }
                for (; i < n; ++i) { acc += *p; p += S; }
                g_sp[seg][v] = acc;
            }
        }
    }
    grid_bar(1u * GRID);

    // ===== Phase 1.5: fold 3 partials -> s[v] =====
    {
        const int gid = b * 256 + tid;
        if (gid < VOCAB)
            g_s[gid] = g_sp[0][gid] + g_sp[1][gid] + g_sp[2][gid];
    }
    grid_bar(2u * GRID);

    // ===== Phase 2: hidden partials; block (e, v-quarter) =====
    if (b < 512) {
        const int e   = b >> 2;
        const int q   = b & 3;
        const int vlo = q * CHUNK4;
        const int vhi = min(VOCAB, vlo + CHUNK4);
        const float* wr = Wq + (size_t)e * VOCAB;
        float acc = 0.f;
#pragma unroll 4
        for (int v = vlo + tid; v < vhi; v += 256)
            acc += g_s[v] * wr[v];
        acc = blockReduceSum(acc, sh_red);
        if (tid == 0) g_hp[q][e] = acc;
    }
    grid_bar(3u * GRID);

    // ===== Phase 3: logits for this block's v-range + (m_b, Z_b) =====
    const int v0  = b * VPB;
    const int cnt = min(VPB, VOCAB - v0);        // >= 22 for every block
    {
        if (tid < EMB)
            sh_hid[tid] = (g_hp[0][tid] + g_hp[1][tid] + g_hp[2][tid] + g_hp[3][tid])
                          * inv_len + bq[tid];
        __syncthreads();

        const int lane = tid & 31, warp = tid >> 5;
        const float4 h4 = reinterpret_cast<const float4*>(sh_hid)[lane];
        float wmax = -3.402823466e38f;
        for (int k = warp; k < cnt; k += 8) {
            const int v = v0 + k;
            const float4 w4 = reinterpret_cast<const float4*>(Ww + (size_t)v * EMB)[lane];
            float p = w4.x * h4.x + w4.y * h4.y + w4.z * h4.z + w4.w * h4.w;
#pragma unroll
            for (int o = 16; o; o >>= 1) p += __shfl_xor_sync(0xffffffffu, p, o);
            const float lg = p + __ldg(bw + v);
            if (lane == 0) sh_log[k] = lg;
            wmax = fmaxf(wmax, lg);
        }
        if (lane == 0) sh_red[warp] = wmax;
        __syncthreads();
        if (tid == 0) {
            float m = sh_red[0];
#pragma unroll
            for (int i = 1; i < 8; ++i) m = fmaxf(m, sh_red[i]);
            sh_bc = m;
        }
        __syncthreads();
        const float m_b = sh_bc;
        __syncthreads();  // protect sh_red reuse inside blockReduceSum
        float ez = (tid < cnt) ? expf(sh_log[tid] - m_b) : 0.f;
        const float Z = blockReduceSum(ez, sh_red);
        if (tid == 0) { g_m[b] = m_b; g_z[b] = Z; }
    }
    grid_bar(4u * GRID);

    // ===== Phase 4: merge (m,Z) pairs -> LSE; write output from smem =====
    {
        float lm = -3.402823466e38f;
        for (int i = tid; i < GRID; i += 256) lm = fmaxf(lm, g_m[i]);
        float M = blockReduceMax(lm, sh_red);
        if (tid == 0) sh_bc = M;
        __syncthreads();
        M = sh_bc;
        __syncthreads();
        float lz = 0.f;
        for (int i = tid; i < GRID; i += 256) lz += g_z[i] * expf(g_m[i] - M);
        const float Z = blockReduceSum(lz, sh_red);
        if (tid == 0) sh_bc = M + logf(Z);
        __syncthreads();
        const float lse = sh_bc;
        if (tid < cnt) out[v0 + tid] = sh_log[tid] - lse;
    }

    // ===== Reset barrier state for next graph replay =====
    __threadfence();
    __syncthreads();
    if (tid == 0) {
        const unsigned old = atomicAdd(&g_done, 1u);
        if (old == GRID - 1u) {        // last block of the whole grid
            g_barrier = 0u;            // nobody spins anymore: all passed barrier 4
            g_done    = 0u;
            __threadfence();
        }
    }
}

// ---------------- launch -----------------------------------------------------
extern "C" void kernel_launch(void* const* d_in, const int* in_sizes, int n_in,
                              void* d_out, int out_size) {
    const float* oh = (const float*)d_in[0];
    // d_in[1] is the scalar `length` (== CTX); rows derived from shape
    const float* Wq = (const float*)d_in[2];
    const float* bq = (const float*)d_in[3];
    const float* Ww = (const float*)d_in[4];
    const float* bw = (const float*)d_in[5];
    float* out = (float*)d_out;

    const int rows = in_sizes[0] / VOCAB;       // 200
    const float inv_len = 1.0f / (float)rows;   // length == CTX here

    w2v_persist<<<GRID, 256>>>(oh, Wq, bq, Ww, bw, out, rows, inv_len);
}

// round 4
// speedup vs baseline: 1.2736x; 1.1753x over previous
#include <cuda_runtime.h>
#include <math.h>

#define VOCAB 50257
#define EMB   128
#define GRID  592          // <= 148 SMs * 6 guaranteed-resident blocks -> fully co-resident
#define NB1   197          // phase-1 v-blocks (197*256 = 50432 >= VOCAB)
#define TSEG  3            // phase-1 t-segments
#define CHUNK4 ((VOCAB + 3) / 4)   // 12565
#define VPB   85           // v per block in phase 3/4 (592*85 = 50320 >= VOCAB)

// ---------------- persistent scratch (no allocations allowed) ----------------
__device__ float    g_sp[TSEG][NB1 * 256];  // phase-1 partial column sums
__device__ float    g_hp[4][EMB];           // hidden partials (4 v-chunks)
__device__ float    g_m[GRID];              // per-block logit max
__device__ float    g_z[GRID];              // per-block sum exp(l - m_b)
__device__ unsigned g_barrier = 0;          // monotone arrival counter (reset each run)
__device__ unsigned g_done    = 0;          // completion counter for reset

// ---------------- grid barrier with nanosleep backoff ------------------------
__device__ __forceinline__ void grid_bar(unsigned target) {
    __syncthreads();
    if (threadIdx.x == 0) {
        __threadfence();
        unsigned arrived = atomicAdd(&g_barrier, 1u) + 1u;
        if (arrived < target) {
            volatile unsigned* p = &g_barrier;
            while (*p < target) __nanosleep(64);
        }
        __threadfence();
    }
    __syncthreads();
}

// ---------------- block reductions (fixed order -> deterministic) -----------
__device__ __forceinline__ float blockReduceSum(float v, float* sm) {
    int lane = threadIdx.x & 31, warp = threadIdx.x >> 5;
#pragma unroll
    for (int o = 16; o; o >>= 1) v += __shfl_xor_sync(0xffffffffu, v, o);
    if (lane == 0) sm[warp] = v;
    __syncthreads();
    v = (warp == 0 && lane < 8) ? sm[lane] : 0.f;
    if (warp == 0) {
#pragma unroll
        for (int o = 4; o; o >>= 1) v += __shfl_xor_sync(0xffffffffu, v, o);
    }
    return v;  // valid on thread 0
}

__device__ __forceinline__ float blockReduceMax(float v, float* sm) {
    int lane = threadIdx.x & 31, warp = threadIdx.x >> 5;
#pragma unroll
    for (int o = 16; o; o >>= 1) v = fmaxf(v, __shfl_xor_sync(0xffffffffu, v, o));
    if (lane == 0) sm[warp] = v;
    __syncthreads();
    v = (warp == 0 && lane < 8) ? sm[lane] : -3.402823466e38f;
    if (warp == 0) {
#pragma unroll
        for (int o = 4; o; o >>= 1) v = fmaxf(v, __shfl_xor_sync(0xffffffffu, v, o));
    }
    return v;  // valid on thread 0
}

// ---------------- the single persistent kernel ------------------------------
__global__ void __launch_bounds__(256, 6)
w2v_persist(const float* __restrict__ oh, const float* __restrict__ Wq,
            const float* __restrict__ bq, const float* __restrict__ Ww,
            const float* __restrict__ bw, float* __restrict__ out,
            int rows, float inv_len)
{
    __shared__ float sh_hid[EMB];
    __shared__ float sh_log[96];
    __shared__ float sh_red[8];
    __shared__ float sh_bc;

    const int tid = threadIdx.x;
    const int b   = blockIdx.x;

    // ===== Phase 1: partial column sums of text_onehot (3 t-segments) =====
    {
        const int seg = b / NB1;                 // 0..2 for b<591, b==591 idle
        if (seg < TSEG) {
            const int v = (b - seg * NB1) * 256 + tid;
            if (v < VOCAB) {
                const int rp = (rows + TSEG - 1) / TSEG;
                const int t0 = seg * rp;
                const int t1 = min(rows, t0 + rp);
                const size_t S = (size_t)VOCAB;
                const float* p = oh + (size_t)t0 * S + v;
                float acc = 0.f;
                int n = t1 - t0, i = 0;
                for (; i + 8 <= n; i += 8) {
                    float a0 = p[0*S], a1 = p[1*S], a2 = p[2*S], a3 = p[3*S];
                    float a4 = p[4*S], a5 = p[5*S], a6 = p[6*S], a7 = p[7*S];
                    acc += ((a0 + a1) + (a2 + a3)) + ((a4 + a5) + (a6 + a7));
                    p += 8 * S;
                }
                for (; i < n; ++i) { acc += *p; p += S; }
                g_sp[seg][v] = acc;
            }
        }
    }
    grid_bar(1u * GRID);

    // ===== Phase 2: hidden partials; block (e, v-quarter); folds s inline ===
    if (b < 512) {
        const int e   = b >> 2;
        const int q   = b & 3;
        const int vlo = q * CHUNK4;
        const int vhi = min(VOCAB, vlo + CHUNK4);
        const float* wr = Wq + (size_t)e * VOCAB;
        float acc = 0.f;
#pragma unroll 4
        for (int v = vlo + tid; v < vhi; v += 256) {
            const float s = g_sp[0][v] + g_sp[1][v] + g_sp[2][v];
            acc += s * wr[v];
        }
        acc = blockReduceSum(acc, sh_red);
        if (tid == 0) g_hp[q][e] = acc;
    }
    grid_bar(2u * GRID);

    // ===== Phase 3: logits for this block's v-range + (m_b, Z_b) =====
    const int v0  = b * VPB;
    const int cnt = min(VPB, VOCAB - v0);        // >= 22 for every block
    {
        if (tid < EMB)
            sh_hid[tid] = (g_hp[0][tid] + g_hp[1][tid] + g_hp[2][tid] + g_hp[3][tid])
                          * inv_len + bq[tid];
        __syncthreads();

        const int lane = tid & 31, warp = tid >> 5;
        const float4 h4 = reinterpret_cast<const float4*>(sh_hid)[lane];
        float wmax = -3.402823466e38f;
        // two rows in flight per iteration: independent loads, interleaved chains
        for (int k = warp; k < cnt; k += 16) {
            const int k2ok = (k + 8) < cnt;
            const int vA = v0 + k;
            const int vB = v0 + k + (k2ok ? 8 : 0);
            const float4 wA = reinterpret_cast<const float4*>(Ww + (size_t)vA * EMB)[lane];
            const float4 wB = reinterpret_cast<const float4*>(Ww + (size_t)vB * EMB)[lane];
            float pA = wA.x * h4.x + wA.y * h4.y + wA.z * h4.z + wA.w * h4.w;
            float pB = wB.x * h4.x + wB.y * h4.y + wB.z * h4.z + wB.w * h4.w;
#pragma unroll
            for (int o = 16; o; o >>= 1) {
                pA += __shfl_xor_sync(0xffffffffu, pA, o);
                pB += __shfl_xor_sync(0xffffffffu, pB, o);
            }
            const float lgA = pA + __ldg(bw + vA);
            if (lane == 0) sh_log[k] = lgA;
            wmax = fmaxf(wmax, lgA);
            if (k2ok) {
                const float lgB = pB + __ldg(bw + vB);
                if (lane == 0) sh_log[k + 8] = lgB;
                wmax = fmaxf(wmax, lgB);
            }
        }
        if (lane == 0) sh_red[warp] = wmax;
        __syncthreads();
        if (tid == 0) {
            float m = sh_red[0];
#pragma unroll
            for (int i = 1; i < 8; ++i) m = fmaxf(m, sh_red[i]);
            sh_bc = m;
        }
        __syncthreads();
        const float m_b = sh_bc;
        __syncthreads();  // protect sh_red reuse inside blockReduceSum
        float ez = (tid < cnt) ? expf(sh_log[tid] - m_b) : 0.f;
        const float Z = blockReduceSum(ez, sh_red);
        if (tid == 0) { g_m[b] = m_b; g_z[b] = Z; }
    }
    grid_bar(3u * GRID);

    // ===== Phase 4: merge (m,Z) pairs -> LSE; write output from smem =====
    {
        float lm = -3.402823466e38f;
        for (int i = tid; i < GRID; i += 256) lm = fmaxf(lm, g_m[i]);
        float M = blockReduceMax(lm, sh_red);
        if (tid == 0) sh_bc = M;
        __syncthreads();
        M = sh_bc;
        __syncthreads();
        float lz = 0.f;
        for (int i = tid; i < GRID; i += 256) lz += g_z[i] * expf(g_m[i] - M);
        const float Z = blockReduceSum(lz, sh_red);
        if (tid == 0) sh_bc = M + logf(Z);
        __syncthreads();
        const float lse = sh_bc;
        if (tid < cnt) out[v0 + tid] = sh_log[tid] - lse;
    }

    // ===== Reset barrier state for next graph replay =====
    __threadfence();
    __syncthreads();
    if (tid == 0) {
        const unsigned old = atomicAdd(&g_done, 1u);
        if (old == GRID - 1u) {        // last block of the whole grid
            g_barrier = 0u;            // nobody spins anymore: all passed barrier 3
            g_done    = 0u;
            __threadfence();
        }
    }
}

// ---------------- launch -----------------------------------------------------
extern "C" void kernel_launch(void* const* d_in, const int* in_sizes, int n_in,
                              void* d_out, int out_size) {
    const float* oh = (const float*)d_in[0];
    // d_in[1] is the scalar `length` (== CTX); rows derived from shape
    const float* Wq = (const float*)d_in[2];
    const float* bq = (const float*)d_in[3];
    const float* Ww = (const float*)d_in[4];
    const float* bw = (const float*)d_in[5];
    float* out = (float*)d_out;

    const int rows = in_sizes[0] / VOCAB;       // 200
    const float inv_len = 1.0f / (float)rows;   // length == CTX here

    w2v_persist<<<GRID, 256>>>(oh, Wq, bq, Ww, bw, out, rows, inv_len);
}